// round 8
// baseline (speedup 1.0000x reference)
#include <cuda_runtime.h>
#include <cuda_fp16.h>

// ---------------- problem constants ----------------
#define Bn   32
#define Tn   8
#define Dd   768
#define DHh  3072
#define Ff   512
#define MHh  128
#define Pp   196
#define BP   (Bn*Pp)

// ---------------- device scratch (fp16 single pass) ----------------
__device__ __half g_pH  [(long)BP*Dd];
__device__ __half g_hH  [(long)BP*Dd];
__device__ __half g_hbH [(long)BP*Dd];
__device__ __half g_W1sH[(long)Dd*Dd];
__device__ __half g_W2sH[(long)Dd*DHh];
__device__ __half g_W1bH[(long)Bn*Dd*Dd];
__device__ __half g_W2bH[(long)Bn*Dd*DHh];
__device__ float g_h2m0[Bn*DHh], g_h2m1[Bn*DHh];
__device__ float g_base[Bn*Ff],  g_coef[Bn*Tn];
__device__ float g_b1b[Bn*Dd],   g_b2b[Bn*DHh];
__device__ float g_z0[Bn*Ff],    g_y[(long)Tn*Bn*Ff];

// ---------------- helpers ----------------
__device__ __forceinline__ unsigned pack_h2(float a, float b) {
    __half2 h = __floats2half2_rn(a, b);
    return *reinterpret_cast<unsigned*>(&h);
}
__device__ __forceinline__ void mma_f16(float* c, const unsigned* a, const unsigned* b) {
    asm volatile(
        "mma.sync.aligned.m16n8k16.row.col.f32.f16.f16.f32 "
        "{%0,%1,%2,%3}, {%4,%5,%6,%7}, {%8,%9}, {%0,%1,%2,%3};"
        : "+f"(c[0]), "+f"(c[1]), "+f"(c[2]), "+f"(c[3])
        : "r"(a[0]), "r"(a[1]), "r"(a[2]), "r"(a[3]), "r"(b[0]), "r"(b[1]));
}
__device__ __forceinline__ void ldsm_x4(unsigned* r, unsigned addr) {
    asm volatile("ldmatrix.sync.aligned.m8n8.x4.shared.b16 {%0,%1,%2,%3}, [%4];"
                 : "=r"(r[0]), "=r"(r[1]), "=r"(r[2]), "=r"(r[3]) : "r"(addr));
}
__device__ __forceinline__ void ldsm_x4t(unsigned* r, unsigned addr) {
    asm volatile("ldmatrix.sync.aligned.m8n8.x4.trans.shared.b16 {%0,%1,%2,%3}, [%4];"
                 : "=r"(r[0]), "=r"(r[1]), "=r"(r[2]), "=r"(r[3]) : "r"(addr));
}
__device__ __forceinline__ void cp16(unsigned smem, const void* g, int srcBytes) {
    asm volatile("cp.async.cg.shared.global [%0], [%1], 16, %2;"
                 :: "r"(smem), "l"(g), "r"(srcBytes));
}
#define CP_COMMIT() asm volatile("cp.async.commit_group;")
#define CP_WAIT1()  asm volatile("cp.async.wait_group 1;")

// ---------------- patchify: x -> fp16 ----------------
__global__ void patchify_h(const float* __restrict__ x, __half* __restrict__ p) {
    long q = (long)blockIdx.x * blockDim.x + threadIdx.x;
    if (q >= (long)BP * Dd / 2) return;
    int d2   = (int)(q % (Dd / 2));
    long rem = q / (Dd / 2);
    int patch = (int)(rem % Pp);
    int b     = (int)(rem / Pp);
    int d  = d2 * 2;
    int pi = patch / 14, pj = patch % 14;
    int c = d >> 8, r = (d >> 4) & 15, s = d & 15;
    float2 v = *(const float2*)(x + ((long)(b * 3 + c) * 224 + pi * 16 + r) * 224 + pj * 16 + s);
    *(unsigned*)(p + rem * Dd + d) = pack_h2(v.x, v.y);
}

// ---------------- convert fp32 weight -> fp16 ----------------
__global__ void cvt_w(const float* __restrict__ src, __half* __restrict__ dst, long n4) {
    long i = (long)blockIdx.x * blockDim.x + threadIdx.x;
    if (i >= n4) return;
    float4 v = *(const float4*)(src + i * 4);
    *(uint2*)(dst + i * 4) = make_uint2(pack_h2(v.x, v.y), pack_h2(v.z, v.w));
}

// ---------------- zero two buffers ----------------
__global__ void zero2(float* a, float* b, int n) {
    int i = blockIdx.x * blockDim.x + threadIdx.x;
    if (i < n) { a[i] = 0.f; b[i] = 0.f; }
}

// ---------------- tensor-core batched GEMM (fp16, 128x128x32, 3-stage cp.async) ----
#define BM 128
#define BN 128
#define BK 32
#define NSTAGE 3
#define APITCH 40    // halves per A row (32 data + 8 pad) = 80B
#define BPITCH 136   // halves per B row (128 data + 8 pad) = 272B
#define A_ST (BM*APITCH)            // halves per A stage
#define B_ST (BK*BPITCH)            // halves per B stage
#define STAGE_H (A_ST + B_ST)
#define SMEM_BYTES (NSTAGE*STAGE_H*2)

__global__ void __launch_bounds__(256) mma_gemm4(
    const __half* __restrict__ aH, long aStride,
    const __half* __restrict__ wH, long wStride,
    const float* __restrict__ bias, long biasStride,
    __half* cH, long cStride,
    float* pool,
    int M, int N, int K, int mode)
{
    int bz = blockIdx.z;
    aH   += (long)bz * aStride;
    wH   += (long)bz * wStride;
    bias += (long)bz * biasStride;

    extern __shared__ __half smem[];

    int m0 = blockIdx.x * BM;
    int n0 = blockIdx.y * BN;
    int tid  = threadIdx.x;
    int lane = tid & 31;
    int warp = tid >> 5;
    int wm = warp & 3;        // 4 m-warps (32 rows)
    int wn = warp >> 2;       // 2 n-warps (64 cols)

    unsigned sBase = (unsigned)__cvta_generic_to_shared(&smem[0]);

    // cp.async mappings
    int aRow = tid >> 2, aChunk = tid & 3;     // A: 128 rows x 4 chunks (x2 iters of 256)
    int bRow = tid >> 4, bChunk = tid & 15;    // B: 32 rows x 16 chunks (x2 iters)

    int ntile = K / BK;

    auto prefetch = [&](int t) {
        int k0 = t * BK;
        unsigned st = (unsigned)(t % NSTAGE) * STAGE_H * 2 + sBase;
        #pragma unroll
        for (int i = 0; i < 2; i++) {
            int row = aRow + i * 64;
            int gm  = m0 + row;
            const __half* src = aH + (long)min(gm, M - 1) * K + k0 + aChunk * 8;
            cp16(st + (unsigned)((row * APITCH + aChunk * 8) * 2), src, gm < M ? 16 : 0);
        }
        unsigned bst = st + (unsigned)(A_ST * 2);
        #pragma unroll
        for (int i = 0; i < 2; i++) {
            int row = bRow + i * 16;
            const __half* src = wH + (long)(k0 + row) * N + n0 + bChunk * 8;
            cp16(bst + (unsigned)((row * BPITCH + bChunk * 8) * 2), src, 16);
        }
    };

    // ldmatrix addresses (within a stage)
    unsigned aAddr[2][2];   // [kstep][mt]
    #pragma unroll
    for (int ks = 0; ks < 2; ks++)
        #pragma unroll
        for (int mt = 0; mt < 2; mt++)
            aAddr[ks][mt] = (unsigned)(((wm * 32 + mt * 16 + (lane & 15)) * APITCH
                                        + ks * 16 + (lane >> 4) * 8) * 2);
    unsigned bAddr[2][4];   // [kstep][ntp]  (each x4t covers 16 cols)
    {
        int krow = (lane & 7) + ((lane >> 3) & 1) * 8;
        int cofs = (lane >> 4) * 8;
        #pragma unroll
        for (int ks = 0; ks < 2; ks++)
            #pragma unroll
            for (int ntp = 0; ntp < 4; ntp++)
                bAddr[ks][ntp] = (unsigned)(((ks * 16 + krow) * BPITCH
                                             + wn * 64 + ntp * 16 + cofs) * 2);
    }

    float acc[2][8][4];
    #pragma unroll
    for (int i = 0; i < 2; i++)
        #pragma unroll
        for (int j = 0; j < 8; j++)
            #pragma unroll
            for (int k = 0; k < 4; k++) acc[i][j][k] = 0.f;

    // prologue: 2 stages in flight
    prefetch(0); CP_COMMIT();
    if (ntile > 1) { prefetch(1); } CP_COMMIT();

    for (int t = 0; t < ntile; t++) {
        CP_WAIT1();
        __syncthreads();
        if (t + 2 < ntile) prefetch(t + 2);
        CP_COMMIT();

        unsigned st  = (unsigned)(t % NSTAGE) * STAGE_H * 2 + sBase;
        unsigned bst = st + (unsigned)(A_ST * 2);

        #pragma unroll
        for (int ks = 0; ks < 2; ks++) {
            unsigned afr[2][4];
            #pragma unroll
            for (int mt = 0; mt < 2; mt++)
                ldsm_x4(afr[mt], st + aAddr[ks][mt]);
            unsigned bfr[4][4];
            #pragma unroll
            for (int ntp = 0; ntp < 4; ntp++)
                ldsm_x4t(bfr[ntp], bst + bAddr[ks][ntp]);
            #pragma unroll
            for (int mt = 0; mt < 2; mt++)
                #pragma unroll
                for (int nt = 0; nt < 8; nt++)
                    mma_f16(acc[mt][nt], afr[mt], &bfr[nt >> 1][(nt & 1) * 2]);
        }
        __syncthreads();
    }

    int g  = lane >> 2;
    int c4 = lane & 3;

    if (mode == 0) {
        cH += (long)bz * cStride;
        #pragma unroll
        for (int mt = 0; mt < 2; mt++) {
            int r0 = m0 + wm * 32 + mt * 16 + g;
            #pragma unroll
            for (int nt = 0; nt < 8; nt++) {
                int col = n0 + wn * 64 + nt * 8 + 2 * c4;
                float bx = bias[col], by = bias[col + 1];
                if (r0 < M) {
                    float v0 = fmaxf(acc[mt][nt][0] + bx, 0.f);
                    float v1 = fmaxf(acc[mt][nt][1] + by, 0.f);
                    *(unsigned*)(cH + (long)r0 * N + col) = pack_h2(v0, v1);
                }
                if (r0 + 8 < M) {
                    float v0 = fmaxf(acc[mt][nt][2] + bx, 0.f);
                    float v1 = fmaxf(acc[mt][nt][3] + by, 0.f);
                    *(unsigned*)(cH + (long)(r0 + 8) * N + col) = pack_h2(v0, v1);
                }
            }
        }
    } else {
        int warpRow0 = m0 + wm * 32;
        if (warpRow0 < M) {
            int sLocal = warpRow0 / Pp;
            int sampA  = bz + sLocal;
            int bnd    = (sLocal + 1) * Pp - warpRow0;
            bool has2  = (bnd < 32) && (warpRow0 + bnd) < M;
            float t0[16], t1[16];
            #pragma unroll
            for (int s = 0; s < 16; s++) { t0[s] = 0.f; t1[s] = 0.f; }
            #pragma unroll
            for (int mt = 0; mt < 2; mt++) {
                int lr0 = mt * 16 + g;
                int lr1 = lr0 + 8;
                bool ok0 = (warpRow0 + lr0) < M;
                bool ok1 = (warpRow0 + lr1) < M;
                #pragma unroll
                for (int nt = 0; nt < 8; nt++) {
                    int col = n0 + wn * 64 + nt * 8 + 2 * c4;
                    float bx = bias[col], by = bias[col + 1];
                    float a0 = fmaxf(acc[mt][nt][0] + bx, 0.f);
                    float a1 = fmaxf(acc[mt][nt][1] + by, 0.f);
                    float a2 = fmaxf(acc[mt][nt][2] + bx, 0.f);
                    float a3 = fmaxf(acc[mt][nt][3] + by, 0.f);
                    int s0 = nt * 2, s1 = nt * 2 + 1;
                    if (ok0) {
                        if (lr0 < bnd) { t0[s0] += a0; t0[s1] += a1; }
                        else           { t1[s0] += a0; t1[s1] += a1; }
                    }
                    if (ok1) {
                        if (lr1 < bnd) { t0[s0] += a2; t0[s1] += a3; }
                        else           { t1[s0] += a2; t1[s1] += a3; }
                    }
                }
            }
            #pragma unroll
            for (int ofs = 4; ofs < 32; ofs <<= 1) {
                #pragma unroll
                for (int s = 0; s < 16; s++)
                    t0[s] += __shfl_xor_sync(0xFFFFFFFFu, t0[s], ofs);
            }
            if (has2) {
                #pragma unroll
                for (int ofs = 4; ofs < 32; ofs <<= 1) {
                    #pragma unroll
                    for (int s = 0; s < 16; s++)
                        t1[s] += __shfl_xor_sync(0xFFFFFFFFu, t1[s], ofs);
                }
            }
            if (lane < 4) {
                const float inv = 1.f / (float)Pp;
                #pragma unroll
                for (int nt = 0; nt < 8; nt++) {
                    #pragma unroll
                    for (int cp = 0; cp < 2; cp++) {
                        int col = n0 + wn * 64 + nt * 8 + 2 * lane + cp;
                        atomicAdd(&pool[(long)sampA * N + col], t0[nt * 2 + cp] * inv);
                        if (has2)
                            atomicAdd(&pool[(long)(sampA + 1) * N + col], t1[nt * 2 + cp] * inv);
                    }
                }
            }
        }
    }
}

// ---------------- small-M GEMM with in-block split-K ----------------
__global__ void rowgemm_kernel(const float* __restrict__ A,
                               const float* __restrict__ W, long wStride,
                               const float* __restrict__ bias, long biasStride,
                               float* __restrict__ C, int N, int K)
{
    int b  = blockIdx.x;
    int nl = threadIdx.x & 31;
    int kg = threadIdx.x >> 5;
    int n  = blockIdx.y * 32 + nl;
    const float* a = A + (long)b * K;
    const float* w = W + (long)b * wStride;
    int kchunk = K / 8;
    float acc = 0.f;
    for (int k = kg * kchunk; k < (kg + 1) * kchunk; k++)
        acc = fmaf(a[k], w[(long)k * N + n], acc);
    __shared__ float red[8][32];
    red[kg][nl] = acc;
    __syncthreads();
    if (kg == 0) {
        float s = acc;
        #pragma unroll
        for (int j = 1; j < 8; j++) s += red[j][nl];
        C[(long)b * N + n] = s + bias[(long)b * biasStride + n];
    }
}

// ---------------- MetaNet ----------------
__global__ void meta_kernel(const float* __restrict__ base,
                            const float* __restrict__ mW1, const float* __restrict__ mb1,
                            const float* __restrict__ mW2, const float* __restrict__ mb2,
                            float* __restrict__ coef)
{
    int b = blockIdx.x;
    __shared__ float br[Ff];
    __shared__ float hid[MHh];
    int t = threadIdx.x;
    for (int i = t; i < Ff; i += MHh) br[i] = base[b * Ff + i];
    __syncthreads();
    float acc = mb1[t];
    for (int e = 0; e < Ff; e++) acc = fmaf(br[e], mW1[e * MHh + t], acc);
    hid[t] = fmaxf(acc, 0.f);
    __syncthreads();
    if (t < Tn) {
        float c = mb2[t];
        for (int j = 0; j < MHh; j++) c = fmaf(hid[j], mW2[j * Tn + t], c);
        coef[b * Tn + t] = c;
    }
}

// ---------------- compose biases (fp32) ----------------
__global__ void compose_kernel(const float* __restrict__ W, const float* __restrict__ dW,
                               const float* __restrict__ coef, float* __restrict__ out, long S)
{
    __shared__ float cs[Bn * Tn];
    if (threadIdx.x < Bn * Tn) cs[threadIdx.x] = coef[threadIdx.x];
    __syncthreads();
    long i = (long)blockIdx.x * blockDim.x + threadIdx.x;
    if (i >= S) return;
    float w = W[i];
    float d[Tn];
    #pragma unroll
    for (int t = 0; t < Tn; t++) d[t] = dW[(long)t * S + i];
    #pragma unroll 4
    for (int b = 0; b < Bn; b++) {
        float v = w;
        #pragma unroll
        for (int t = 0; t < Tn; t++) v = fmaf(cs[b * Tn + t], d[t], v);
        out[(long)b * S + i] = v;
    }
}

// ---------------- compose weights -> fp16 ----------------
__global__ void compose_h(const float* __restrict__ W, const float* __restrict__ dW,
                          const float* __restrict__ coef, __half* __restrict__ oH, long S)
{
    __shared__ float cs[Bn * Tn];
    if (threadIdx.x < Bn * Tn) cs[threadIdx.x] = coef[threadIdx.x];
    __syncthreads();
    long q = (long)blockIdx.x * blockDim.x + threadIdx.x;
    if (q >= S / 4) return;
    long e = q * 4;
    float4 w = *(const float4*)(W + e);
    float4 d[Tn];
    #pragma unroll
    for (int t = 0; t < Tn; t++) d[t] = *(const float4*)(dW + (long)t * S + e);
    for (int b = 0; b < Bn; b++) {
        float4 v = w;
        #pragma unroll
        for (int t = 0; t < Tn; t++) {
            float c = cs[b * Tn + t];
            v.x = fmaf(c, d[t].x, v.x);
            v.y = fmaf(c, d[t].y, v.y);
            v.z = fmaf(c, d[t].z, v.z);
            v.w = fmaf(c, d[t].w, v.w);
        }
        *(uint2*)(oH + (long)b * S + e) = make_uint2(pack_h2(v.x, v.y), pack_h2(v.z, v.w));
    }
}

// ---------------- y[t,b,n] = h2m[b,:] @ dW3[t,:,n] ----------------
#define YNC 16
__global__ void ydw3_kernel(const float* __restrict__ h2m, const float* __restrict__ dW3,
                            float* __restrict__ y)
{
    int t  = blockIdx.y;
    int n0 = blockIdx.x * YNC;
    const float* w = dW3 + (long)t * DHh * Ff;
    __shared__ float sw[16][YNC];
    __shared__ float sh[Bn][16];
    int tid = threadIdx.x;
    int b  = tid >> 3;
    int nl = tid & 7;
    float acc0 = 0.f, acc1 = 0.f;
    for (int k0 = 0; k0 < DHh; k0 += 16) {
        if (tid < 64) {
            int kk = tid >> 2, nq = tid & 3;
            float4 v = *(const float4*)(w + (long)(k0 + kk) * Ff + n0 + nq * 4);
            sw[kk][nq * 4 + 0] = v.x; sw[kk][nq * 4 + 1] = v.y;
            sw[kk][nq * 4 + 2] = v.z; sw[kk][nq * 4 + 3] = v.w;
        }
        if (tid >= 128) {
            int tt = tid - 128;
            int bb = tt >> 2, kq = tt & 3;
            float4 v = *(const float4*)(h2m + (long)bb * DHh + k0 + kq * 4);
            sh[bb][kq * 4 + 0] = v.x; sh[bb][kq * 4 + 1] = v.y;
            sh[bb][kq * 4 + 2] = v.z; sh[bb][kq * 4 + 3] = v.w;
        }
        __syncthreads();
        #pragma unroll
        for (int kk = 0; kk < 16; kk++) {
            float a = sh[b][kk];
            acc0 = fmaf(a, sw[kk][nl * 2 + 0], acc0);
            acc1 = fmaf(a, sw[kk][nl * 2 + 1], acc1);
        }
        __syncthreads();
    }
    long o = ((long)t * Bn + b) * Ff + n0 + nl * 2;
    y[o]     = acc0;
    y[o + 1] = acc1;
}

// ---------------- final combine ----------------
__global__ void combine_kernel(const float* __restrict__ z0, const float* __restrict__ y,
                               const float* __restrict__ coef, const float* __restrict__ db3,
                               float* __restrict__ out)
{
    int i = blockIdx.x * blockDim.x + threadIdx.x;
    if (i >= Bn * Ff) return;
    int b = i / Ff, n = i % Ff;
    float v = z0[i];
    #pragma unroll
    for (int t = 0; t < Tn; t++)
        v = fmaf(coef[b * Tn + t], y[((long)t * Bn + b) * Ff + n] + db3[t * Ff + n], v);
    out[i] = v;
}

// ---------------- launch ----------------
extern "C" void kernel_launch(void* const* d_in, const int* in_sizes, int n_in,
                              void* d_out, int out_size)
{
    const float* x   = (const float*)d_in[0];
    const float* W1  = (const float*)d_in[1];
    const float* b1  = (const float*)d_in[2];
    const float* W2  = (const float*)d_in[3];
    const float* b2  = (const float*)d_in[4];
    const float* W3  = (const float*)d_in[5];
    const float* b3  = (const float*)d_in[6];
    const float* dW1 = (const float*)d_in[7];
    const float* db1 = (const float*)d_in[8];
    const float* dW2 = (const float*)d_in[9];
    const float* db2 = (const float*)d_in[10];
    const float* dW3 = (const float*)d_in[11];
    const float* db3 = (const float*)d_in[12];
    const float* mW1 = (const float*)d_in[13];
    const float* mb1 = (const float*)d_in[14];
    const float* mW2 = (const float*)d_in[15];
    const float* mb2 = (const float*)d_in[16];
    float* out = (float*)d_out;

    __half *pH, *hH, *hbH, *W1sH, *W2sH, *W1bH, *W2bH;
    float *h2m0, *h2m1, *base, *coef, *b1b, *b2b, *z0, *y;
    cudaGetSymbolAddress((void**)&pH,   g_pH);
    cudaGetSymbolAddress((void**)&hH,   g_hH);
    cudaGetSymbolAddress((void**)&hbH,  g_hbH);
    cudaGetSymbolAddress((void**)&W1sH, g_W1sH);
    cudaGetSymbolAddress((void**)&W2sH, g_W2sH);
    cudaGetSymbolAddress((void**)&W1bH, g_W1bH);
    cudaGetSymbolAddress((void**)&W2bH, g_W2bH);
    cudaGetSymbolAddress((void**)&h2m0, g_h2m0);
    cudaGetSymbolAddress((void**)&h2m1, g_h2m1);
    cudaGetSymbolAddress((void**)&base, g_base);
    cudaGetSymbolAddress((void**)&coef, g_coef);
    cudaGetSymbolAddress((void**)&b1b,  g_b1b);
    cudaGetSymbolAddress((void**)&b2b,  g_b2b);
    cudaGetSymbolAddress((void**)&z0,   g_z0);
    cudaGetSymbolAddress((void**)&y,    g_y);

    cudaFuncSetAttribute(mma_gemm4,
                         cudaFuncAttributeMaxDynamicSharedMemorySize, SMEM_BYTES);

    // 1) patchify -> fp16
    {
        long n = (long)BP * Dd / 2;
        patchify_h<<<(unsigned)((n + 255) / 256), 256>>>(x, pH);
    }
    // 2) convert base weights to fp16
    cvt_w<<<(unsigned)(((long)Dd * Dd / 4 + 255) / 256), 256>>>(W1, W1sH, (long)Dd * Dd / 4);
    cvt_w<<<(unsigned)(((long)Dd * DHh / 4 + 255) / 256), 256>>>(W2, W2sH, (long)Dd * DHh / 4);
    // 3) zero pool accumulators
    zero2<<<(Bn * DHh + 255) / 256, 256>>>(h2m0, h2m1, Bn * DHh);

    // 4) base layer1: h = relu(p @ W1 + b1)
    mma_gemm4<<<dim3(BP / BM, Dd / BN, 1), 256, SMEM_BYTES>>>(
        pH, 0, W1sH, 0, b1, 0,
        hH, 0, nullptr, BP, Dd, Dd, 0);

    // 5) base layer2 + fused mean-pool -> h2m0
    mma_gemm4<<<dim3(BP / BM, DHh / BN, 1), 256, SMEM_BYTES>>>(
        hH, 0, W2sH, 0, b2, 0,
        nullptr, 0, h2m0, BP, DHh, Dd, 1);

    // 6) base = h2m0 @ W3 + b3
    rowgemm_kernel<<<dim3(Bn, Ff / 32), 256>>>(h2m0, W3, 0, b3, 0, base, Ff, DHh);

    // 7) MetaNet -> coefs
    meta_kernel<<<Bn, MHh>>>(base, mW1, mb1, mW2, mb2, coef);

    // 8) compose biases + weights (fp16)
    compose_kernel<<<(Dd  + 255) / 256, 256>>>(b1, db1, coef, b1b, Dd);
    compose_kernel<<<(DHh + 255) / 256, 256>>>(b2, db2, coef, b2b, DHh);
    {
        long S1 = (long)Dd * Dd;
        long S2 = (long)Dd * DHh;
        compose_h<<<(unsigned)((S1 / 4 + 255) / 256), 256>>>(W1, dW1, coef, W1bH, S1);
        compose_h<<<(unsigned)((S2 / 4 + 255) / 256), 256>>>(W2, dW2, coef, W2bH, S2);
    }

    // 9) adapted layer1 (batched): hb = relu(p @ W1b + b1b)
    mma_gemm4<<<dim3((Pp + BM - 1) / BM, Dd / BN, Bn), 256, SMEM_BYTES>>>(
        pH,   (long)Pp * Dd,
        W1bH, (long)Dd * Dd,
        b1b,  (long)Dd,
        hbH,  (long)Pp * Dd, nullptr,
        Pp, Dd, Dd, 0);

    // 10) adapted layer2 + fused mean-pool -> h2m1
    mma_gemm4<<<dim3((Pp + BM - 1) / BM, DHh / BN, Bn), 256, SMEM_BYTES>>>(
        hbH,  (long)Pp * Dd,
        W2bH, (long)Dd * DHh,
        b2b,  (long)DHh,
        nullptr, 0, h2m1,
        Pp, DHh, Dd, 1);

    // 11) z0 = h2m1 @ W3 + b3
    rowgemm_kernel<<<dim3(Bn, Ff / 32), 256>>>(h2m1, W3, 0, b3, 0, z0, Ff, DHh);

    // 12) y[t,b,:] = h2m1[b,:] @ dW3[t]
    ydw3_kernel<<<dim3(Ff / YNC, Tn), 256>>>(h2m1, dW3, y);

    // 13) out = z0 + sum_t coef*(y + db3)
    combine_kernel<<<(Bn * Ff + 255) / 256, 256>>>(z0, y, coef, db3, out);
}